// round 13
// baseline (speedup 1.0000x reference)
#include <cuda_runtime.h>
#include <cuda_bf16.h>
#include <cstdint>

// Shapes (fixed by the problem)
#define B 4
#define C 256
#define NHEADS 8
#define DK 32
#define TN 2304            // H*W
#define BH (B * NHEADS)
#define NBLK (TN / 8)      // 288 8-row token blocks
#define SCALE 0.17677669529663687f  // 1/sqrt(32)
#define LOG2E 1.4426950408889634f
#define ONES_BF16X2 0x3F803F80u

// Fragment-ordered bf16 scratch (u32 words):
__device__ uint32_t g_qt[BH * NBLK * 2 * 64];
__device__ uint32_t g_kt[BH * NBLK * 2 * 64];
__device__ uint32_t g_v [BH * 4 * 144 * 64];
__device__ uint32_t g_xf[B * NBLK * 16 * 64];
__device__ uint32_t g_wf[3 * 32 * 16 * 64];

// ---------------------------------------------------------------------------
__device__ __forceinline__ uint32_t ex2_bf16x2(uint32_t x) {
    uint32_t y;
    asm("ex2.approx.ftz.bf16x2 %0, %1;" : "=r"(y) : "r"(x));
    return y;
}

__device__ __forceinline__ uint32_t pack_bf16(float lo, float hi) {
    uint32_t r;
    asm("cvt.rn.bf16x2.f32 %0, %1, %2;" : "=r"(r) : "f"(hi), "f"(lo));
    return r;
}

__device__ __forceinline__ void mma_bf16(float c[4],
                                         uint32_t a0, uint32_t a1, uint32_t a2, uint32_t a3,
                                         uint32_t b0, uint32_t b1) {
    asm volatile(
        "mma.sync.aligned.m16n8k16.row.col.f32.bf16.bf16.f32 "
        "{%0,%1,%2,%3}, {%4,%5,%6,%7}, {%8,%9}, {%0,%1,%2,%3};"
        : "+f"(c[0]), "+f"(c[1]), "+f"(c[2]), "+f"(c[3])
        : "r"(a0), "r"(a1), "r"(a2), "r"(a3), "r"(b0), "r"(b1));
}

// ---------------------------------------------------------------------------
// prep: merged W + X conversion into fragment-ordered bf16 blocks.
// blocks [0,192): W (wq scaled by SCALE*LOG2E); blocks [192, 2496): X.
// ---------------------------------------------------------------------------
__global__ __launch_bounds__(256) void prep_kernel(
    const float* __restrict__ wq,
    const float* __restrict__ wk,
    const float* __restrict__ wv,
    const float* __restrict__ x,
    uint32_t* __restrict__ wf,
    uint32_t* __restrict__ xf)
{
    int bid = blockIdx.x;
    if (bid < 192) {
        int t = bid * 256 + threadIdx.x;         // 0 .. 49151
        int proj = t >> 14;
        int r = t & 16383;
        int lane = r & 31;
        int kc = (r >> 5) & 15;
        int blk = r >> 9;
        int o  = blk * 8 + (lane >> 2);
        int tg = lane & 3;
        int c0 = kc * 16 + tg * 2;

        const float* w = (proj == 0) ? wq : (proj == 1) ? wk : wv;
        float s = (proj == 0) ? (SCALE * LOG2E) : 1.0f;

        float2 lo = *(const float2*)(w + o * C + c0);
        float2 hi = *(const float2*)(w + o * C + c0 + 8);
        uint2 out;
        out.x = pack_bf16(lo.x * s, lo.y * s);
        out.y = pack_bf16(hi.x * s, hi.y * s);
        *(uint2*)(wf + ((size_t)(proj * 32 + blk) * 16 + kc) * 64 + lane * 2) = out;
    } else {
        int xb_id = bid - 192;
        int b = xb_id / 576;
        int t = (xb_id % 576) * 256 + threadIdx.x;   // 0 .. 147455
        int lane = t & 31;
        int kc = (t >> 5) & 15;
        int blk = t >> 9;
        int n  = blk * 8 + (lane >> 2);
        int tg = lane & 3;
        int c0 = kc * 16 + tg * 2;

        const float* xb = x + (size_t)b * C * TN;
        float a0 = xb[(size_t)(c0    ) * TN + n];
        float a1 = xb[(size_t)(c0 + 1) * TN + n];
        float a2 = xb[(size_t)(c0 + 8) * TN + n];
        float a3 = xb[(size_t)(c0 + 9) * TN + n];
        uint2 out;
        out.x = pack_bf16(a0, a1);
        out.y = pack_bf16(a2, a3);
        *(uint2*)(xf + ((size_t)(b * NBLK + blk) * 16 + kc) * 64 + lane * 2) = out;
    }
}

// ---------------------------------------------------------------------------
// Fused projection GEMM, bf16 HMMA, zero smem. grid (18, 12, B).
// ---------------------------------------------------------------------------
__global__ __launch_bounds__(128) void proj_kernel(
    const uint32_t* __restrict__ xf,
    const uint32_t* __restrict__ wf,
    uint32_t* __restrict__ qt,
    uint32_t* __restrict__ kt,
    uint32_t* __restrict__ vt)
{
    const int tid  = threadIdx.x;
    const int warp = tid >> 5;
    const int lane = tid & 31;
    const int gid  = lane >> 2;
    const int tig  = lane & 3;

    const int b    = blockIdx.z;
    const int proj = blockIdx.y >> 2;
    const int ob   = (blockIdx.y & 3) * 64;
    const int rw   = blockIdx.x * 128 + warp * 32;

    const uint32_t* xb = xf + ((size_t)(b * NBLK + (rw >> 3)) * 16) * 64;
    const uint32_t* wb = wf + ((size_t)(proj * 32 + (ob >> 3)) * 16) * 64;

    float acc[2][8][4];
#pragma unroll
    for (int mt = 0; mt < 2; mt++)
#pragma unroll
        for (int nt = 0; nt < 8; nt++)
#pragma unroll
            for (int r = 0; r < 4; r++) acc[mt][nt][r] = 0.f;

#pragma unroll
    for (int kc = 0; kc < 16; kc++) {
        uint32_t a[2][4];
#pragma unroll
        for (int mt = 0; mt < 2; mt++) {
            const uint32_t* p = xb + ((size_t)(mt * 2) * 16 + kc) * 64 + lane * 2;
            uint2 w0 = *(const uint2*)p;
            uint2 w1 = *(const uint2*)(p + 16 * 64);
            a[mt][0] = w0.x; a[mt][1] = w1.x; a[mt][2] = w0.y; a[mt][3] = w1.y;
        }
#pragma unroll
        for (int nt = 0; nt < 8; nt++) {
            uint2 bv = *(const uint2*)(wb + ((size_t)nt * 16 + kc) * 64 + lane * 2);
#pragma unroll
            for (int mt = 0; mt < 2; mt++)
                mma_bf16(acc[mt][nt], a[mt][0], a[mt][1], a[mt][2], a[mt][3],
                         bv.x, bv.y);
        }
    }

    if (proj < 2) {
        uint32_t* dst = (proj == 0) ? qt : kt;
#pragma unroll
        for (int ntp = 0; ntp < 4; ntp++) {
            int nt0 = 2 * ntp;
            int o   = ob + nt0 * 8 + 2 * tig;
            int h   = o >> 5;
            int bh  = b * NHEADS + h;
            int kcq = (o >> 4) & 1;
            size_t cbase = (size_t)bh * (NBLK * 128) + (size_t)kcq * 64
                         + (gid * 4 + tig) * 2;
#pragma unroll
            for (int mt = 0; mt < 2; mt++) {
                int n = rw + mt * 16 + gid;
                size_t addr = cbase + (size_t)(n >> 3) * 128;
                uint2 wlo, whi;
                wlo.x = pack_bf16(acc[mt][nt0    ][0], acc[mt][nt0    ][1]);
                wlo.y = pack_bf16(acc[mt][nt0 + 1][0], acc[mt][nt0 + 1][1]);
                whi.x = pack_bf16(acc[mt][nt0    ][2], acc[mt][nt0    ][3]);
                whi.y = pack_bf16(acc[mt][nt0 + 1][2], acc[mt][nt0 + 1][3]);
                *(uint2*)(dst + addr)       = wlo;
                *(uint2*)(dst + addr + 128) = whi;
            }
        }
    } else {
        bool even = (gid & 1) == 0;
#pragma unroll
        for (int nt = 0; nt < 8; nt++) {
            int o = ob + nt * 8 + 2 * tig + (even ? 0 : 1);
            int d8 = (o & 31) >> 3;
            int bh = b * NHEADS + (o >> 5);
            size_t base = ((size_t)bh * 4 + d8) * (144 * 64);
#pragma unroll
            for (int mt = 0; mt < 2; mt++) {
                float c0 = acc[mt][nt][0], c1 = acc[mt][nt][1];
                float c2 = acc[mt][nt][2], c3 = acc[mt][nt][3];
                float t0 = __shfl_xor_sync(0xffffffffu, c0, 4);
                float t1 = __shfl_xor_sync(0xffffffffu, c1, 4);
                float t2 = __shfl_xor_sync(0xffffffffu, c2, 4);
                float t3 = __shfl_xor_sync(0xffffffffu, c3, 4);
                int n   = rw + mt * 16 + gid;
                int key = n - (gid & 1);
                uint2 wv;
                if (even) { wv.x = pack_bf16(c0, t0); wv.y = pack_bf16(c2, t2); }
                else      { wv.x = pack_bf16(t1, c1); wv.y = pack_bf16(t3, c3); }
                size_t addr = base + (size_t)(key >> 4) * 64
                            + ((o & 7) * 4 + ((key >> 1) & 3)) * 2;
                *(uint2*)(vt + addr) = wv;
            }
        }
    }
}

// ---------------------------------------------------------------------------
// Flash attention: same math as R12, but 16 queries per warp, 32-thread CTAs.
// grid = (TN/16, NHEADS, B) = (144, 8, 4) = 4608 CTAs -> RF-limited ~19
// warps/SM instead of grid-limited 14, to fill tensor-pipe gaps.
// ---------------------------------------------------------------------------
__global__ __launch_bounds__(32, 16) void attn_kernel(
    const uint32_t* __restrict__ qt,
    const uint32_t* __restrict__ kt,
    const uint32_t* __restrict__ v,
    const float* __restrict__ x,
    float* __restrict__ out)
{
    const int lane = threadIdx.x;
    const int gid  = lane >> 2;
    const int tig  = lane & 3;

    const int n0 = blockIdx.x * 16;
    const int bh = blockIdx.z * NHEADS + blockIdx.y;
    const uint32_t* qtb = qt + (size_t)bh * NBLK * 128;
    const uint32_t* ktb = kt + (size_t)bh * NBLK * 128;
    const uint32_t* vb  = v  + (size_t)bh * 4 * 144 * 64;

    // ---- Q fragments: 16 rows (2 row-blocks), pre-scaled ----
    uint32_t qa[2][4];
    {
        int jq = n0 >> 3;
#pragma unroll
        for (int kc = 0; kc < 2; kc++) {
            const uint32_t* p = qtb + (size_t)jq * 128 + kc * 64 + lane * 2;
            uint2 w0 = *(const uint2*)p;
            uint2 w1 = *(const uint2*)(p + 128);
            qa[kc][0] = w0.x;
            qa[kc][1] = w1.x;
            qa[kc][2] = w0.y;
            qa[kc][3] = w1.y;
        }
    }

    float o[4][4];
    float lacc[4];
#pragma unroll
    for (int r = 0; r < 4; r++) lacc[r] = 0.f;
#pragma unroll
    for (int nt = 0; nt < 4; nt++)
#pragma unroll
        for (int r = 0; r < 4; r++) o[nt][r] = 0.f;

    for (int j0 = 0; j0 < TN; j0 += 32) {
        uint32_t kf[4][2][2], vf[4][2][2];
        {
            const uint32_t* kp = ktb + (size_t)(j0 >> 3) * 128 + lane * 2;
#pragma unroll
            for (int nt = 0; nt < 4; nt++)
#pragma unroll
                for (int kc = 0; kc < 2; kc++) {
                    uint2 wv = *(const uint2*)(kp + nt * 128 + kc * 64);
                    kf[nt][kc][0] = wv.x; kf[nt][kc][1] = wv.y;
                }
            const uint32_t* vp = vb + (size_t)(j0 >> 4) * 64 + lane * 2;
#pragma unroll
            for (int nt = 0; nt < 4; nt++)
#pragma unroll
                for (int kc = 0; kc < 2; kc++) {
                    uint2 wv = *(const uint2*)(vp + (size_t)nt * 144 * 64 + kc * 64);
                    vf[nt][kc][0] = wv.x; vf[nt][kc][1] = wv.y;
                }
        }

        // ---- S = Q K^T : 8 MMAs ----
        float sc[4][4];
#pragma unroll
        for (int nt = 0; nt < 4; nt++)
#pragma unroll
            for (int r = 0; r < 4; r++) sc[nt][r] = 0.f;

#pragma unroll
        for (int kc = 0; kc < 2; kc++)
#pragma unroll
            for (int nt = 0; nt < 4; nt++)
                mma_bf16(sc[nt], qa[kc][0], qa[kc][1], qa[kc][2], qa[kc][3],
                         kf[nt][kc][0], kf[nt][kc][1]);

        // ---- pack + exp (MUFU bf16x2): 8 ops ----
        uint32_t pa[2][4];
#pragma unroll
        for (int p = 0; p < 2; p++) {
            pa[p][0] = ex2_bf16x2(pack_bf16(sc[2*p  ][0], sc[2*p  ][1]));
            pa[p][1] = ex2_bf16x2(pack_bf16(sc[2*p  ][2], sc[2*p  ][3]));
            pa[p][2] = ex2_bf16x2(pack_bf16(sc[2*p+1][0], sc[2*p+1][1]));
            pa[p][3] = ex2_bf16x2(pack_bf16(sc[2*p+1][2], sc[2*p+1][3]));
        }

        // ---- O += P V (8 MMAs) ;  l += P @ ones (2 MMAs) ----
#pragma unroll
        for (int p = 0; p < 2; p++) {
#pragma unroll
            for (int nt = 0; nt < 4; nt++)
                mma_bf16(o[nt], pa[p][0], pa[p][1], pa[p][2], pa[p][3],
                         vf[nt][p][0], vf[nt][p][1]);
            mma_bf16(lacc, pa[p][0], pa[p][1], pa[p][2], pa[p][3],
                     ONES_BF16X2, ONES_BF16X2);
        }
    }

    // ---- normalize (lacc c0 = row gid sum, c2 = row gid+8 sum) ----
    float inv0 = 1.f / lacc[0];
    float inv1 = 1.f / lacc[2];

    __shared__ float psf[16 * 36];
#pragma unroll
    for (int nt = 0; nt < 4; nt++) {
        int col = nt * 8 + 2 * tig;
        psf[(gid    ) * 36 + col    ] = o[nt][0] * inv0;
        psf[(gid    ) * 36 + col + 1] = o[nt][1] * inv0;
        psf[(gid + 8) * 36 + col    ] = o[nt][2] * inv1;
        psf[(gid + 8) * 36 + col + 1] = o[nt][3] * inv1;
    }
    __syncwarp();

    const size_t head_off = (size_t)bh * DK * TN;
#pragma unroll
    for (int t = 0; t < 4; t++) {
        int idx = lane + t * 32;          // 0..127 float4 units
        int d = idx >> 2, nv = idx & 3;
        size_t gaddr = head_off + (size_t)d * TN + n0 + nv * 4;
        float4 xv = *(const float4*)(x + gaddr);
        float4 ov;
        ov.x = xv.x + psf[(nv * 4 + 0) * 36 + d];
        ov.y = xv.y + psf[(nv * 4 + 1) * 36 + d];
        ov.z = xv.z + psf[(nv * 4 + 2) * 36 + d];
        ov.w = xv.w + psf[(nv * 4 + 3) * 36 + d];
        *(float4*)(out + gaddr) = ov;
    }
}

// ---------------------------------------------------------------------------
extern "C" void kernel_launch(void* const* d_in, const int* in_sizes, int n_in,
                              void* d_out, int out_size)
{
    const float* x  = (const float*)d_in[0];
    const float* wq = (const float*)d_in[1];
    const float* wk = (const float*)d_in[2];
    const float* wv = (const float*)d_in[3];
    float* out = (float*)d_out;

    uint32_t* qt; cudaGetSymbolAddress((void**)&qt, g_qt);
    uint32_t* kt; cudaGetSymbolAddress((void**)&kt, g_kt);
    uint32_t* vt; cudaGetSymbolAddress((void**)&vt, g_v);
    uint32_t* xf; cudaGetSymbolAddress((void**)&xf, g_xf);
    uint32_t* wf; cudaGetSymbolAddress((void**)&wf, g_wf);

    prep_kernel<<<2496, 256>>>(wq, wk, wv, x, wf, xf);
    proj_kernel<<<dim3(18, 12, B), 128>>>(xf, wf, qt, kt, vt);
    attn_kernel<<<dim3(TN / 16, NHEADS, B), 32>>>(qt, kt, vt, x, out);
}

// round 14
// speedup vs baseline: 1.0813x; 1.0813x over previous
#include <cuda_runtime.h>
#include <cuda_bf16.h>
#include <cstdint>

// Shapes (fixed by the problem)
#define B 4
#define C 256
#define NHEADS 8
#define DK 32
#define TN 2304            // H*W
#define BH (B * NHEADS)
#define NBLK (TN / 8)      // 288 8-row token blocks
#define SCALE 0.17677669529663687f  // 1/sqrt(32)
#define LOG2E 1.4426950408889634f
#define ONES_BF16X2 0x3F803F80u

// Fragment-ordered bf16 scratch (u32 words):
__device__ uint32_t g_qt[BH * NBLK * 2 * 64];
__device__ uint32_t g_kt[BH * NBLK * 2 * 64];
__device__ uint32_t g_v [BH * 4 * 144 * 64];
__device__ uint32_t g_xf[B * NBLK * 16 * 64];
__device__ uint32_t g_wf[3 * 32 * 16 * 64];

// ---------------------------------------------------------------------------
__device__ __forceinline__ uint32_t ex2_bf16x2(uint32_t x) {
    uint32_t y;
    asm("ex2.approx.ftz.bf16x2 %0, %1;" : "=r"(y) : "r"(x));
    return y;
}

__device__ __forceinline__ uint32_t pack_bf16(float lo, float hi) {
    uint32_t r;
    asm("cvt.rn.bf16x2.f32 %0, %1, %2;" : "=r"(r) : "f"(hi), "f"(lo));
    return r;
}

__device__ __forceinline__ void mma_bf16(float c[4],
                                         uint32_t a0, uint32_t a1, uint32_t a2, uint32_t a3,
                                         uint32_t b0, uint32_t b1) {
    asm volatile(
        "mma.sync.aligned.m16n8k16.row.col.f32.bf16.bf16.f32 "
        "{%0,%1,%2,%3}, {%4,%5,%6,%7}, {%8,%9}, {%0,%1,%2,%3};"
        : "+f"(c[0]), "+f"(c[1]), "+f"(c[2]), "+f"(c[3])
        : "r"(a0), "r"(a1), "r"(a2), "r"(a3), "r"(b0), "r"(b1));
}

// ---------------------------------------------------------------------------
// prep: merged W + X conversion into fragment-ordered bf16 blocks.
// ---------------------------------------------------------------------------
__global__ __launch_bounds__(256) void prep_kernel(
    const float* __restrict__ wq,
    const float* __restrict__ wk,
    const float* __restrict__ wv,
    const float* __restrict__ x,
    uint32_t* __restrict__ wf,
    uint32_t* __restrict__ xf)
{
    int bid = blockIdx.x;
    if (bid < 192) {
        int t = bid * 256 + threadIdx.x;
        int proj = t >> 14;
        int r = t & 16383;
        int lane = r & 31;
        int kc = (r >> 5) & 15;
        int blk = r >> 9;
        int o  = blk * 8 + (lane >> 2);
        int tg = lane & 3;
        int c0 = kc * 16 + tg * 2;

        const float* w = (proj == 0) ? wq : (proj == 1) ? wk : wv;
        float s = (proj == 0) ? (SCALE * LOG2E) : 1.0f;

        float2 lo = *(const float2*)(w + o * C + c0);
        float2 hi = *(const float2*)(w + o * C + c0 + 8);
        uint2 out;
        out.x = pack_bf16(lo.x * s, lo.y * s);
        out.y = pack_bf16(hi.x * s, hi.y * s);
        *(uint2*)(wf + ((size_t)(proj * 32 + blk) * 16 + kc) * 64 + lane * 2) = out;
    } else {
        int xb_id = bid - 192;
        int b = xb_id / 576;
        int t = (xb_id % 576) * 256 + threadIdx.x;
        int lane = t & 31;
        int kc = (t >> 5) & 15;
        int blk = t >> 9;
        int n  = blk * 8 + (lane >> 2);
        int tg = lane & 3;
        int c0 = kc * 16 + tg * 2;

        const float* xb = x + (size_t)b * C * TN;
        float a0 = xb[(size_t)(c0    ) * TN + n];
        float a1 = xb[(size_t)(c0 + 1) * TN + n];
        float a2 = xb[(size_t)(c0 + 8) * TN + n];
        float a3 = xb[(size_t)(c0 + 9) * TN + n];
        uint2 out;
        out.x = pack_bf16(a0, a1);
        out.y = pack_bf16(a2, a3);
        *(uint2*)(xf + ((size_t)(b * NBLK + blk) * 16 + kc) * 64 + lane * 2) = out;
    }
}

// ---------------------------------------------------------------------------
// Fused projection GEMM, bf16 HMMA, zero smem. grid (18, 12, B).
// ---------------------------------------------------------------------------
__global__ __launch_bounds__(128) void proj_kernel(
    const uint32_t* __restrict__ xf,
    const uint32_t* __restrict__ wf,
    uint32_t* __restrict__ qt,
    uint32_t* __restrict__ kt,
    uint32_t* __restrict__ vt)
{
    const int tid  = threadIdx.x;
    const int warp = tid >> 5;
    const int lane = tid & 31;
    const int gid  = lane >> 2;
    const int tig  = lane & 3;

    const int b    = blockIdx.z;
    const int proj = blockIdx.y >> 2;
    const int ob   = (blockIdx.y & 3) * 64;
    const int rw   = blockIdx.x * 128 + warp * 32;

    const uint32_t* xb = xf + ((size_t)(b * NBLK + (rw >> 3)) * 16) * 64;
    const uint32_t* wb = wf + ((size_t)(proj * 32 + (ob >> 3)) * 16) * 64;

    float acc[2][8][4];
#pragma unroll
    for (int mt = 0; mt < 2; mt++)
#pragma unroll
        for (int nt = 0; nt < 8; nt++)
#pragma unroll
            for (int r = 0; r < 4; r++) acc[mt][nt][r] = 0.f;

#pragma unroll
    for (int kc = 0; kc < 16; kc++) {
        uint32_t a[2][4];
#pragma unroll
        for (int mt = 0; mt < 2; mt++) {
            const uint32_t* p = xb + ((size_t)(mt * 2) * 16 + kc) * 64 + lane * 2;
            uint2 w0 = *(const uint2*)p;
            uint2 w1 = *(const uint2*)(p + 16 * 64);
            a[mt][0] = w0.x; a[mt][1] = w1.x; a[mt][2] = w0.y; a[mt][3] = w1.y;
        }
#pragma unroll
        for (int nt = 0; nt < 8; nt++) {
            uint2 bv = *(const uint2*)(wb + ((size_t)nt * 16 + kc) * 64 + lane * 2);
#pragma unroll
            for (int mt = 0; mt < 2; mt++)
                mma_bf16(acc[mt][nt], a[mt][0], a[mt][1], a[mt][2], a[mt][3],
                         bv.x, bv.y);
        }
    }

    if (proj < 2) {
        uint32_t* dst = (proj == 0) ? qt : kt;
#pragma unroll
        for (int ntp = 0; ntp < 4; ntp++) {
            int nt0 = 2 * ntp;
            int o   = ob + nt0 * 8 + 2 * tig;
            int h   = o >> 5;
            int bh  = b * NHEADS + h;
            int kcq = (o >> 4) & 1;
            size_t cbase = (size_t)bh * (NBLK * 128) + (size_t)kcq * 64
                         + (gid * 4 + tig) * 2;
#pragma unroll
            for (int mt = 0; mt < 2; mt++) {
                int n = rw + mt * 16 + gid;
                size_t addr = cbase + (size_t)(n >> 3) * 128;
                uint2 wlo, whi;
                wlo.x = pack_bf16(acc[mt][nt0    ][0], acc[mt][nt0    ][1]);
                wlo.y = pack_bf16(acc[mt][nt0 + 1][0], acc[mt][nt0 + 1][1]);
                whi.x = pack_bf16(acc[mt][nt0    ][2], acc[mt][nt0    ][3]);
                whi.y = pack_bf16(acc[mt][nt0 + 1][2], acc[mt][nt0 + 1][3]);
                *(uint2*)(dst + addr)       = wlo;
                *(uint2*)(dst + addr + 128) = whi;
            }
        }
    } else {
        bool even = (gid & 1) == 0;
#pragma unroll
        for (int nt = 0; nt < 8; nt++) {
            int o = ob + nt * 8 + 2 * tig + (even ? 0 : 1);
            int d8 = (o & 31) >> 3;
            int bh = b * NHEADS + (o >> 5);
            size_t base = ((size_t)bh * 4 + d8) * (144 * 64);
#pragma unroll
            for (int mt = 0; mt < 2; mt++) {
                float c0 = acc[mt][nt][0], c1 = acc[mt][nt][1];
                float c2 = acc[mt][nt][2], c3 = acc[mt][nt][3];
                float t0 = __shfl_xor_sync(0xffffffffu, c0, 4);
                float t1 = __shfl_xor_sync(0xffffffffu, c1, 4);
                float t2 = __shfl_xor_sync(0xffffffffu, c2, 4);
                float t3 = __shfl_xor_sync(0xffffffffu, c3, 4);
                int n   = rw + mt * 16 + gid;
                int key = n - (gid & 1);
                uint2 wv;
                if (even) { wv.x = pack_bf16(c0, t0); wv.y = pack_bf16(c2, t2); }
                else      { wv.x = pack_bf16(t1, c1); wv.y = pack_bf16(t3, c3); }
                size_t addr = base + (size_t)(key >> 4) * 64
                            + ((o & 7) * 4 + ((key >> 1) & 3)) * 2;
                *(uint2*)(vt + addr) = wv;
            }
        }
    }
}

// ---------------------------------------------------------------------------
// Flash attention: R12 shape (64-thread CTAs, 32 q/warp) with software-
// pipelined fragment loads: next-tile K loads issue right after the S-phase
// consumes kf; next-tile V loads right after PV consumes vf. Zero extra regs.
// ---------------------------------------------------------------------------
__global__ __launch_bounds__(64, 8) void attn_kernel(
    const uint32_t* __restrict__ qt,
    const uint32_t* __restrict__ kt,
    const uint32_t* __restrict__ v,
    const float* __restrict__ x,
    float* __restrict__ out)
{
    const int tid  = threadIdx.x;
    const int warp = tid >> 5;
    const int lane = tid & 31;
    const int gid  = lane >> 2;
    const int tig  = lane & 3;

    const int n0 = blockIdx.x * 64;
    const int bh = blockIdx.z * NHEADS + blockIdx.y;
    const uint32_t* qtb = qt + (size_t)bh * NBLK * 128;
    const uint32_t* ktb = kt + (size_t)bh * NBLK * 128;
    const uint32_t* vb  = v  + (size_t)bh * 4 * 144 * 64;

    uint32_t qa[2][2][4];
    {
        int jq = (n0 >> 3) + warp * 4;
#pragma unroll
        for (int mt = 0; mt < 2; mt++)
#pragma unroll
            for (int kc = 0; kc < 2; kc++) {
                const uint32_t* p = qtb + (size_t)(jq + mt * 2) * 128 + kc * 64 + lane * 2;
                uint2 w0 = *(const uint2*)p;
                uint2 w1 = *(const uint2*)(p + 128);
                qa[mt][kc][0] = w0.x;
                qa[mt][kc][1] = w1.x;
                qa[mt][kc][2] = w0.y;
                qa[mt][kc][3] = w1.y;
            }
    }

    float o[2][4][4];
    float lacc[2][4];
#pragma unroll
    for (int mt = 0; mt < 2; mt++) {
#pragma unroll
        for (int r = 0; r < 4; r++) lacc[mt][r] = 0.f;
#pragma unroll
        for (int nt = 0; nt < 4; nt++)
#pragma unroll
            for (int r = 0; r < 4; r++) o[mt][nt][r] = 0.f;
    }

    uint32_t kf[4][2][2], vf[4][2][2];

    auto loadK = [&](int j0) {
        const uint32_t* kp = ktb + (size_t)(j0 >> 3) * 128 + lane * 2;
#pragma unroll
        for (int nt = 0; nt < 4; nt++)
#pragma unroll
            for (int kc = 0; kc < 2; kc++) {
                uint2 wv = *(const uint2*)(kp + nt * 128 + kc * 64);
                kf[nt][kc][0] = wv.x; kf[nt][kc][1] = wv.y;
            }
    };
    auto loadV = [&](int j0) {
        const uint32_t* vp = vb + (size_t)(j0 >> 4) * 64 + lane * 2;
#pragma unroll
        for (int nt = 0; nt < 4; nt++)
#pragma unroll
            for (int kc = 0; kc < 2; kc++) {
                uint2 wv = *(const uint2*)(vp + (size_t)nt * 144 * 64 + kc * 64);
                vf[nt][kc][0] = wv.x; vf[nt][kc][1] = wv.y;
            }
    };

    loadK(0);
    loadV(0);

    for (int j0 = 0; j0 < TN; j0 += 32) {
        int jn = (j0 + 32 < TN) ? (j0 + 32) : j0;   // last iter: harmless reload

        // ---- S = Q K^T : 16 MMAs (kf dies here) ----
        float sc[2][4][4];
#pragma unroll
        for (int mt = 0; mt < 2; mt++)
#pragma unroll
            for (int nt = 0; nt < 4; nt++)
#pragma unroll
                for (int r = 0; r < 4; r++) sc[mt][nt][r] = 0.f;

#pragma unroll
        for (int kc = 0; kc < 2; kc++)
#pragma unroll
            for (int nt = 0; nt < 4; nt++)
#pragma unroll
                for (int mt = 0; mt < 2; mt++)
                    mma_bf16(sc[mt][nt], qa[mt][kc][0], qa[mt][kc][1],
                             qa[mt][kc][2], qa[mt][kc][3],
                             kf[nt][kc][0], kf[nt][kc][1]);

        // ---- prefetch next-tile K while exp/PV run ----
        loadK(jn);

        // ---- pack + exp (MUFU bf16x2) ----
        uint32_t pa[2][2][4];
#pragma unroll
        for (int mt = 0; mt < 2; mt++)
#pragma unroll
            for (int p = 0; p < 2; p++) {
                pa[mt][p][0] = ex2_bf16x2(pack_bf16(sc[mt][2*p  ][0], sc[mt][2*p  ][1]));
                pa[mt][p][1] = ex2_bf16x2(pack_bf16(sc[mt][2*p  ][2], sc[mt][2*p  ][3]));
                pa[mt][p][2] = ex2_bf16x2(pack_bf16(sc[mt][2*p+1][0], sc[mt][2*p+1][1]));
                pa[mt][p][3] = ex2_bf16x2(pack_bf16(sc[mt][2*p+1][2], sc[mt][2*p+1][3]));
            }

        // ---- O += P V ; l += P @ ones (vf dies here) ----
#pragma unroll
        for (int p = 0; p < 2; p++)
#pragma unroll
            for (int mt = 0; mt < 2; mt++) {
#pragma unroll
                for (int nt = 0; nt < 4; nt++)
                    mma_bf16(o[mt][nt], pa[mt][p][0], pa[mt][p][1],
                             pa[mt][p][2], pa[mt][p][3],
                             vf[nt][p][0], vf[nt][p][1]);
                mma_bf16(lacc[mt], pa[mt][p][0], pa[mt][p][1],
                         pa[mt][p][2], pa[mt][p][3],
                         ONES_BF16X2, ONES_BF16X2);
            }

        // ---- prefetch next-tile V (in flight through next S+exp) ----
        loadV(jn);
    }

    // ---- normalize (lacc c0 = row gid sum, c2 = row gid+8 sum) ----
    float inv[2][2];
#pragma unroll
    for (int mt = 0; mt < 2; mt++) {
        inv[mt][0] = 1.f / lacc[mt][0];
        inv[mt][1] = 1.f / lacc[mt][2];
    }

    __shared__ float psf[64 * 36];
#pragma unroll
    for (int mt = 0; mt < 2; mt++) {
        int rb = warp * 32 + mt * 16;
#pragma unroll
        for (int nt = 0; nt < 4; nt++) {
            int col = nt * 8 + 2 * tig;
            psf[(rb + gid    ) * 36 + col    ] = o[mt][nt][0] * inv[mt][0];
            psf[(rb + gid    ) * 36 + col + 1] = o[mt][nt][1] * inv[mt][0];
            psf[(rb + gid + 8) * 36 + col    ] = o[mt][nt][2] * inv[mt][1];
            psf[(rb + gid + 8) * 36 + col + 1] = o[mt][nt][3] * inv[mt][1];
        }
    }
    __syncthreads();

    const size_t head_off = (size_t)bh * DK * TN;
#pragma unroll
    for (int t = 0; t < 8; t++) {
        int idx = tid + t * 64;
        int d = idx >> 4, nv = idx & 15;
        size_t gaddr = head_off + (size_t)d * TN + n0 + nv * 4;
        float4 xv = *(const float4*)(x + gaddr);
        float4 ov;
        ov.x = xv.x + psf[(nv * 4 + 0) * 36 + d];
        ov.y = xv.y + psf[(nv * 4 + 1) * 36 + d];
        ov.z = xv.z + psf[(nv * 4 + 2) * 36 + d];
        ov.w = xv.w + psf[(nv * 4 + 3) * 36 + d];
        *(float4*)(out + gaddr) = ov;
    }
}

// ---------------------------------------------------------------------------
extern "C" void kernel_launch(void* const* d_in, const int* in_sizes, int n_in,
                              void* d_out, int out_size)
{
    const float* x  = (const float*)d_in[0];
    const float* wq = (const float*)d_in[1];
    const float* wk = (const float*)d_in[2];
    const float* wv = (const float*)d_in[3];
    float* out = (float*)d_out;

    uint32_t* qt; cudaGetSymbolAddress((void**)&qt, g_qt);
    uint32_t* kt; cudaGetSymbolAddress((void**)&kt, g_kt);
    uint32_t* vt; cudaGetSymbolAddress((void**)&vt, g_v);
    uint32_t* xf; cudaGetSymbolAddress((void**)&xf, g_xf);
    uint32_t* wf; cudaGetSymbolAddress((void**)&wf, g_wf);

    prep_kernel<<<2496, 256>>>(wq, wk, wv, x, wf, xf);
    proj_kernel<<<dim3(18, 12, B), 128>>>(xf, wf, qt, kt, vt);
    attn_kernel<<<dim3(TN / 64, NHEADS, B), 64>>>(qt, kt, vt, x, out);
}